// round 4
// baseline (speedup 1.0000x reference)
#include <cuda_runtime.h>
#include <stdint.h>

#define NB 32
#define NT 15
#define LCAP  1280                 // max set taps per task (18c*7r*10cols = 1260)
#define NTASK (NB*30*8)

// ---------------- device scratch (no cudaMalloc allowed) ----------------
static __device__ __align__(16) int8_t   g_tf0 [NB*18*32*32];  // input fire times (slow path)
static __device__ __align__(16) float    g_w1q [3*882*32];     // w1: [fg][k][32 lanes]
static __device__ __align__(16) uint32_t g_list[(size_t)NTASK*LCAP]; // conv1 tap lists
static __device__              uint32_t g_lcnt[NTASK];         // mid | (tot<<16)
static __device__ __align__(16) int8_t   g_ft1p[NB*90*15*16];  // pooled L1, row-stride 16
static __device__              uint8_t  g_cflag1[NB*90];
static __device__              int      g_any1[NB];
static __device__              float    g_wsat2[250*36];       // SAT of channel-summed w2
static __device__              float    g_wsat3[200*36];       // SAT of channel-summed w3

extern __shared__ unsigned char smem_raw[];

// ===========================================================================
// k_prep: wsat2/3, w1 repack, input fire-times, flag zero, conv1 tap lists.
// Blocks: [0,450) wsat | [450,781) wrep | [781,3085) tf0 | 3085 zero | [3086,3118) lists
__global__ __launch_bounds__(256) void k_prep(const float* __restrict__ inp,
                                              const float* __restrict__ w1,
                                              const float* __restrict__ w2,
                                              const float* __restrict__ w3) {
    int bid = blockIdx.x, tid = threadIdx.x;
    if (bid < 450) {
        __shared__ float s_part[250];
        __shared__ float s25[25];
        const float* src; int C; float* dst; int f;
        if (bid < 250) { f = bid;     src = w2; C = 90;  dst = g_wsat2 + f*36; }
        else           { f = bid-250; src = w3; C = 250; dst = g_wsat3 + f*36; }
        if (tid < 250) {
            int p = tid / 10, g = tid % 10;
            float s = 0.0f;
            for (int c = g; c < C; c += 10) s += src[((size_t)f*C + c)*25 + p];
            s_part[p*10 + g] = s;
        }
        __syncthreads();
        if (tid < 25) {
            float s = 0.0f;
            for (int g = 0; g < 10; g++) s += s_part[tid*10 + g];
            s25[tid] = s;
        }
        __syncthreads();
        if (tid < 36) {
            int i = tid / 6, j = tid % 6;
            float s = 0.0f;
            for (int ii = 0; ii < i; ii++)
                for (int jj = 0; jj < j; jj++) s += s25[ii*5 + jj];
            dst[tid] = s;
        }
    } else if (bid < 781) {
        int idx = (bid - 450)*256 + tid;
        if (idx < 3*882*32) {
            int lane = idx & 31, k = (idx >> 5) % 882, fg = idx / (882*32);
            int f = fg*32 + lane;
            g_w1q[idx] = (f < 90) ? w1[f*882 + k] : 0.0f;
        }
    } else if (bid < 3085) {
        int idx = (bid - 781)*256 + tid;            // exactly 32*18*1024
        int b   = idx / (18*1024);
        int chw = idx - b*(18*1024);
        const float* p = inp + (size_t)b*(NT*18*1024) + chw;
        float s = 0.0f;
#pragma unroll
        for (int t = 0; t < NT; t++) s += p[(size_t)t * 18 * 1024];
        g_tf0[idx] = (int8_t)(15 - (int)(s + 0.5f));
    } else if (bid == 3085) {
        for (int i = tid; i < NB*90; i += 256) g_cflag1[i] = 0;
        if (tid < NB) g_any1[tid] = 0;
    } else {
        // conv1 tap lists for batch b (tf==0 <=> input at t=0 is 1)
        int b = bid - 3086;
        __shared__ uint64_t s_rm[18*32];
        for (int i = tid; i < 18*32; i += 256) {
            int c = i >> 5, h = i & 31;
            const float4* row = (const float4*)(inp + ((size_t)b*NT*18 + c)*1024 + (h << 5));
            uint32_t bits = 0;
#pragma unroll
            for (int k = 0; k < 8; k++) {
                float4 v = row[k];
                bits |= (v.x > 0.5f ? 1u : 0u) << (k*4);
                bits |= (v.y > 0.5f ? 2u : 0u) << (k*4);
                bits |= (v.z > 0.5f ? 4u : 0u) << (k*4);
                bits |= (v.w > 0.5f ? 8u : 0u) << (k*4);
            }
            s_rm[i] = ((uint64_t)bits) << 2;        // bit (w+2) set iff fires at t=0
        }
        __syncthreads();
        if (tid < 240) {
            int y = tid / 8, q = tid & 7, x0 = q*4;
            int task = (b*30 + y)*8 + q;
            uint32_t* out = g_list + (size_t)task * LCAP;
            int n = 0;
            // mid pass: p in [3,6] — serves all 4 pixels unconditionally
            for (int c = 0; c < 18; c++)
#pragma unroll
                for (int i = 0; i < 7; i++) {
                    int h = y + i - 2;
                    if ((unsigned)h >= 32u) continue;
                    uint32_t wnd = (uint32_t)(s_rm[(c << 5) + h] >> x0) & 0x3FFu;
                    uint32_t mm = wnd & 0x078u;
                    int wb = (c*49 + i*7) * 32;
                    while (mm) {
                        int p = __ffs(mm) - 1; mm &= mm - 1;
                        out[n++] = (uint32_t)(wb + (p << 5)) | ((uint32_t)p << 24);
                    }
                }
            int nm = n;
            // edge pass: p in {0,1,2,7,8,9}
            for (int c = 0; c < 18; c++)
#pragma unroll
                for (int i = 0; i < 7; i++) {
                    int h = y + i - 2;
                    if ((unsigned)h >= 32u) continue;
                    uint32_t wnd = (uint32_t)(s_rm[(c << 5) + h] >> x0) & 0x3FFu;
                    uint32_t em = wnd & 0x387u;
                    int wb = (c*49 + i*7) * 32;
                    while (em) {
                        int p = __ffs(em) - 1; em &= em - 1;
                        out[n++] = (uint32_t)(wb + (p << 5)) | ((uint32_t)p << 24);
                    }
                }
            g_lcnt[task] = (uint32_t)nm | ((uint32_t)n << 16);
        }
    }
}

// ===========================================================================
// conv1 slow path (rare): full per-t rescan for one neuron.
__device__ __noinline__ int conv1_slow(const float* __restrict__ w1,
                                       int b, int f, int y, int x) {
    const int8_t* tf = g_tf0 + (size_t)b*18*1024;
    const float* wf = w1 + (size_t)f*882;
    for (int t = 1; t < 15; t++) {
        float cum = 0.0f;
        for (int c = 0; c < 18; c++)
            for (int i = 0; i < 7; i++) {
                int h = y + i - 2;
                if ((unsigned)h >= 32u) continue;
                for (int j = 0; j < 7; j++) {
                    int w = x + j - 2;
                    if ((unsigned)w >= 32u) continue;
                    if (tf[(c << 10) + (h << 5) + w] <= t) cum += wf[c*49 + i*7 + j];
                }
            }
        if (cum > 15.0f) return t;
    }
    return 15;
}

// ===========================================================================
// conv1: lane=filter (32/warp), warp = 4 adjacent x for 2 rows (halves).
// Streams precomputed tap lists; fused 2x2 pool + channel flags.
#define CONV1_SMEM (882*32*4 + 8*32*32)
__global__ __launch_bounds__(1024, 1) void k_conv1(const float* __restrict__ w1) {
    float*  s_w  = (float*)smem_raw;                       // 112896 B
    int8_t* s_ft = (int8_t*)(smem_raw + 882*32*4);         // [8 rows][32 x][32 lanes]
    int tid = threadIdx.x;
    int rq = blockIdx.x, fg = blockIdx.y, b = blockIdx.z;
    int lane = tid & 31, w = tid >> 5;
    int dy = w >> 3, q = w & 7, x0 = q*4;

    const uint4* wsrc = (const uint4*)(g_w1q + (size_t)fg*882*32);
    uint4* wdst = (uint4*)s_w;
    for (int i = tid; i < 882*32/4; i += 1024) wdst[i] = wsrc[i];
    __syncthreads();

    int f = fg*32 + lane;
#pragma unroll
    for (int h2 = 0; h2 < 2; h2++) {
        int r = h2*4 + dy;
        int y = rq*8 + r;
        float a0 = 0.f, a1 = 0.f, a2 = 0.f, a3 = 0.f;
        if (y < 30) {
            int task = (b*30 + y)*8 + q;
            uint32_t cnt = g_lcnt[task];
            int mid = (int)(cnt & 0xFFFFu), tot = (int)(cnt >> 16);
            const uint32_t* L = g_list + (size_t)task*LCAP;
            for (int base = 0; base < mid; base += 32) {
                int idx = base + lane;
                uint32_t e = L[idx < mid ? idx : mid-1];
                int n = min(32, mid - base);
                for (int k2 = 0; k2 < n; k2++) {
                    uint32_t ek = __shfl_sync(0xFFFFFFFFu, e, k2);
                    const float* wp = s_w + (ek & 0xFFFFu) + lane;
                    a0 += wp[0]; a1 += wp[-32]; a2 += wp[-64]; a3 += wp[-96];
                }
            }
            for (int base = mid; base < tot; base += 32) {
                int idx = base + lane;
                uint32_t e = L[idx < tot ? idx : tot-1];
                int n = min(32, tot - base);
                for (int k2 = 0; k2 < n; k2++) {
                    uint32_t ek = __shfl_sync(0xFFFFFFFFu, e, k2);
                    int p = (int)(ek >> 24);
                    const float* wp = s_w + (ek & 0xFFFFu) + lane;
                    if (p <= 6)           a0 += wp[0];
                    if (p >= 1 && p <= 7) a1 += wp[-32];
                    if (p >= 2 && p <= 8) a2 += wp[-64];
                    if (p >= 3)           a3 += wp[-96];
                }
            }
        }
        float aa[4] = {a0, a1, a2, a3};
#pragma unroll
        for (int k = 0; k < 4; k++) {
            int x = x0 + k;
            int ft = 0;
            if (y < 30 && x < 30 && f < 90)
                ft = (aa[k] > 15.0f) ? 0 : conv1_slow(w1, b, f, y, x);
            s_ft[(r*32 + x)*32 + lane] = (int8_t)ft;
        }
    }
    __syncthreads();

    // fused 2x2 min-pool + channel flags (4 pooled rows per block)
    bool nz = false;
    for (int i2 = tid; i2 < 1920; i2 += 1024) {
        int pf = i2 & 31;
        int rest = i2 >> 5;                 // 0..59
        int pcol = rest % 15;
        int pr   = rest / 15;               // 0..3
        int prow = rq*4 + pr;
        int r0 = pr*2, c0 = pcol*2;
        int v0 = s_ft[(r0*32     + c0  )*32 + pf];
        int v1 = s_ft[(r0*32     + c0+1)*32 + pf];
        int v2 = s_ft[((r0+1)*32 + c0  )*32 + pf];
        int v3 = s_ft[((r0+1)*32 + c0+1)*32 + pf];
        int m0 = v0 < v1 ? v0 : v1;
        int m1 = v2 < v3 ? v2 : v3;
        int pv = m0 < m1 ? m0 : m1;
        int ff = fg*32 + pf;
        if (prow < 15 && ff < 90) {
            g_ft1p[((b*90 + ff)*15 + prow)*16 + pcol] = (int8_t)pv;
            if (pv) { g_cflag1[b*90 + ff] = 1; nz = true; }
        }
    }
    int cnt = __syncthreads_count(nz);
    if (tid == 0 && cnt) atomicAdd(&g_any1[b], 1);
}

// ===========================================================================
// k_tail: per-batch conv2 + pool2 + conv3 + winner, all in one block.
#define S_SAT2  0
#define S_SAT3  36000
#define S_TF1   64800
#define S_FT2   86400
#define S_FT2P  128656
#define S_FLAG1 132656
#define S_FLAG2 132752
#define S_LUT2  133008
#define S_LUT3  133696
#define S_RV    133760
#define S_RI    137856
#define TAIL_SMEM 141968
__global__ __launch_bounds__(1024, 1) void k_tail(const float* __restrict__ w2,
                                                  const float* __restrict__ w3,
                                                  float* __restrict__ pot,
                                                  float* __restrict__ cls) {
    float*    s_sat2 = (float*)(smem_raw + S_SAT2);
    float*    s_sat3 = (float*)(smem_raw + S_SAT3);
    int8_t*   s_tf1  = (int8_t*)(smem_raw + S_TF1);
    int8_t*   s_ft2  = (int8_t*)(smem_raw + S_FT2);
    int8_t*   s_ft2p = (int8_t*)(smem_raw + S_FT2P);
    uint8_t*  s_flag1 = (uint8_t*)(smem_raw + S_FLAG1);
    uint8_t*  s_flag2 = (uint8_t*)(smem_raw + S_FLAG2);
    uint32_t* s_lut2 = (uint32_t*)(smem_raw + S_LUT2);
    uint32_t* s_lut3 = (uint32_t*)(smem_raw + S_LUT3);
    float*    s_rv   = (float*)(smem_raw + S_RV);
    int*      s_ri   = (int*)(smem_raw + S_RI);

    int b = blockIdx.x, tid = threadIdx.x;
    int any1 = g_any1[b];

    for (int i = tid; i < 9000; i += 1024) s_sat2[i] = g_wsat2[i];
    for (int i = tid; i < 7200; i += 1024) s_sat3[i] = g_wsat3[i];
    if (any1) {
        const uint4* src = (const uint4*)(g_ft1p + (size_t)b*90*240);
        uint4* dst = (uint4*)s_tf1;
        for (int i = tid; i < 90*240/16; i += 1024) dst[i] = src[i];
        if (tid < 90) s_flag1[tid] = g_cflag1[b*90 + tid];
    }
    if (tid < 250) s_flag2[tid] = 0;
    if (tid < 169) {
        int y = tid / 13, x = tid - y*13;
        int r0 = max(0, y-1), r1 = min(14, y+3);
        int c0 = max(0, x-1), c1 = min(14, x+3);
        int i0 = r0-(y-1), i1 = r1-(y-1), j0 = c0-(x-1), j1 = c1-(x-1);
        s_lut2[tid] = (uint32_t)((i1+1)*6 + (j1+1))
                    | ((uint32_t)(i0*6 + (j1+1)) << 8)
                    | ((uint32_t)((i1+1)*6 + j0) << 16)
                    | ((uint32_t)(i0*6 + j0) << 24);
    }
    if (tid < 16) {
        int y = tid >> 2, x = tid & 3;
        int r0 = max(0, y-2), r1 = min(3, y+2);
        int c0 = max(0, x-2), c1 = min(3, x+2);
        int i0 = r0-(y-2), i1 = r1-(y-2), j0 = c0-(x-2), j1 = c1-(x-2);
        s_lut3[tid] = (uint32_t)((i1+1)*6 + (j1+1))
                    | ((uint32_t)(i0*6 + (j1+1)) << 8)
                    | ((uint32_t)((i1+1)*6 + j0) << 16)
                    | ((uint32_t)(i0*6 + j0) << 24);
    }
    __syncthreads();

    // ---- conv2 (SAT fast path; def[] recompute slow path) ----
    for (int o = tid; o < 250*169; o += 1024) {
        int f = o / 169, pix = o - f*169;
        uint32_t lp = s_lut2[pix];
        const float* S = s_sat2 + f*36;
        float a0 = S[lp & 0xFF] - S[(lp>>8) & 0xFF] - S[(lp>>16) & 0xFF] + S[lp>>24];
        int ft;
        if (!any1) {
            ft = (a0 > 10.0f) ? 0 : 15;
        } else {
            int y = pix / 13, x = pix - y*13;
            int r0 = max(0, y-1), r1 = min(14, y+3);
            int c0 = max(0, x-1), c1 = min(14, x+3);
            float def[15];
#pragma unroll
            for (int t = 0; t < 15; t++) def[t] = 0.f;
            for (int c = 0; c < 90; c++) {
                if (!s_flag1[c]) continue;
                for (int r = r0; r <= r1; r++)
                    for (int cc = c0; cc <= c1; cc++) {
                        int tf = s_tf1[c*240 + r*16 + cc];
                        if (tf) {
                            float wv = __ldg(w2 + ((size_t)f*90 + c)*25 + (r-(y-1))*5 + (cc-(x-1)));
#pragma unroll
                            for (int t = 0; t < 15; t++) def[t] += (tf > t) ? wv : 0.f;
                        }
                    }
            }
            ft = 15;
#pragma unroll
            for (int t = 14; t >= 0; t--) if (a0 - def[t] > 10.0f) ft = t;
        }
        s_ft2[o] = (int8_t)ft;
    }
    __syncthreads();

    // ---- pool2 3x3 s3 + flags ----
    bool nz2 = false;
    for (int i2 = tid; i2 < 4000; i2 += 1024) {
        int f = i2 >> 4, p = i2 & 15;
        int y = (p >> 2)*3, x = (p & 3)*3;
        const int8_t* bp = s_ft2 + f*169 + y*13 + x;
        int v = 15;
#pragma unroll
        for (int dy = 0; dy < 3; dy++)
#pragma unroll
            for (int dx = 0; dx < 3; dx++) {
                int u = bp[dy*13 + dx];
                v = u < v ? u : v;
            }
        s_ft2p[i2] = (int8_t)v;
        if (v) { s_flag2[f] = 1; nz2 = true; }
    }
    int any2 = __syncthreads_count(nz2);

    // ---- conv3 + winner candidates ----
    float bv = 0.f; int bi = 1 << 30;
    for (int o = tid; o < 3200; o += 1024) {
        int f = o >> 4, p = o & 15;
        uint32_t lp = s_lut3[p];
        const float* S = s_sat3 + f*36;
        float a0 = S[lp & 0xFF] - S[(lp>>8) & 0xFF] - S[(lp>>16) & 0xFF] + S[lp>>24];
        float* op = pot + (size_t)b*NT*3200 + o;
        float last;
        if (!any2) {
#pragma unroll
            for (int t = 0; t < NT; t++) op[(size_t)t*3200] = a0;
            last = a0;
        } else {
            int y = p >> 2, x = p & 3;
            int r0 = max(0, y-2), r1 = min(3, y+2);
            int c0 = max(0, x-2), c1 = min(3, x+2);
            float def[15];
#pragma unroll
            for (int t = 0; t < 15; t++) def[t] = 0.f;
            for (int c = 0; c < 250; c++) {
                if (!s_flag2[c]) continue;
                for (int r = r0; r <= r1; r++)
                    for (int cc = c0; cc <= c1; cc++) {
                        int tf = s_ft2p[c*16 + r*4 + cc];
                        if (tf) {
                            float wv = __ldg(w3 + ((size_t)f*250 + c)*25 + (r-(y-2))*5 + (cc-(x-2)));
#pragma unroll
                            for (int t = 0; t < 15; t++) def[t] += (tf > t) ? wv : 0.f;
                        }
                    }
            }
#pragma unroll
            for (int t = 0; t < NT; t++) op[(size_t)t*3200] = a0 - def[t];
            last = a0 - def[14];
        }
        if (last > bv) { bv = last; bi = o; }
    }

    if (cls) {
        s_rv[tid] = bv; s_ri[tid] = bi;
        __syncthreads();
        for (int s = 512; s > 0; s >>= 1) {
            if (tid < s) {
                float ov = s_rv[tid+s]; int oi = s_ri[tid+s];
                if (ov > s_rv[tid] || (ov == s_rv[tid] && oi < s_ri[tid])) {
                    s_rv[tid] = ov; s_ri[tid] = oi;
                }
            }
            __syncthreads();
        }
        if (tid == 0)
            cls[b] = (s_rv[0] > 0.0f) ? (float)((s_ri[0] >> 4) / 20) : -1.0f;
    }
}

// ===========================================================================
extern "C" void kernel_launch(void* const* d_in, const int* in_sizes, int n_in,
                              void* d_out, int out_size) {
    const float* inp = (const float*)d_in[0];
    const float* w1  = (const float*)d_in[1];
    const float* w2  = (const float*)d_in[2];
    const float* w3  = (const float*)d_in[3];

    float* out = (float*)d_out;
    float* pot = out;
    float* cls = nullptr;
    if (out_size == NB + NB*NT*3200) {   // (cls, pot3) concatenated
        cls = out;
        pot = out + NB;
    }

    static bool attr_set = false;
    if (!attr_set) {
        cudaFuncSetAttribute(k_conv1, cudaFuncAttributeMaxDynamicSharedMemorySize,
                             CONV1_SMEM);
        cudaFuncSetAttribute(k_tail, cudaFuncAttributeMaxDynamicSharedMemorySize,
                             TAIL_SMEM);
        attr_set = true;
    }

    k_prep <<<3118, 256>>>(inp, w1, w2, w3);
    k_conv1<<<dim3(4, 3, NB), 1024, CONV1_SMEM>>>(w1);
    k_tail <<<NB, 1024, TAIL_SMEM>>>(w2, w3, pot, cls);
}

// round 5
// speedup vs baseline: 1.0917x; 1.0917x over previous
#include <cuda_runtime.h>
#include <stdint.h>

#define NB 32
#define NT 15

// ---------------- device scratch (no cudaMalloc allowed) ----------------
static __device__ __align__(16) float   g_w1q [3*882*32];      // w1: [fg][k][32 lanes]
static __device__ __align__(16) int8_t  g_ft1p[NB*90*15*16];   // pooled L1, row-stride 16
static __device__              uint8_t g_cflag1[NB*90];
static __device__              int     g_any1[NB];
static __device__ __align__(16) int8_t  g_ft2p[NB*250*16];     // pooled L2 fire times
static __device__              uint8_t g_cflag2[NB*250];
static __device__              int     g_any2[NB];
static __device__              float   g_wsat2[250*36];        // SAT of channel-summed w2
static __device__              float   g_wsat3[200*36];        // SAT of channel-summed w3

extern __shared__ unsigned char smem_raw[];

// ===========================================================================
// k_prep: weight SATs (deterministic), w1 repack, flag zeroing. NO input pass.
// Blocks: [0,250) wsat2 | [250,450) wsat3 | [450,781) wrep | 781 zero.
__global__ __launch_bounds__(256) void k_prep(const float* __restrict__ w1,
                                              const float* __restrict__ w2,
                                              const float* __restrict__ w3) {
    int bid = blockIdx.x, tid = threadIdx.x;
    if (bid < 450) {
        __shared__ float s_part[250];
        __shared__ float s25[25];
        const float* src; int C; float* dst; int f;
        if (bid < 250) { f = bid;     src = w2; C = 90;  dst = g_wsat2 + f*36; }
        else           { f = bid-250; src = w3; C = 250; dst = g_wsat3 + f*36; }
        if (tid < 250) {
            int p = tid / 10, g = tid % 10;
            float s = 0.0f;
            for (int c = g; c < C; c += 10) s += src[((size_t)f*C + c)*25 + p];
            s_part[p*10 + g] = s;
        }
        __syncthreads();
        if (tid < 25) {
            float s = 0.0f;
            for (int g = 0; g < 10; g++) s += s_part[tid*10 + g];
            s25[tid] = s;
        }
        __syncthreads();
        if (tid < 36) {
            int i = tid / 6, j = tid % 6;
            float s = 0.0f;
            for (int ii = 0; ii < i; ii++)
                for (int jj = 0; jj < j; jj++) s += s25[ii*5 + jj];
            dst[tid] = s;
        }
    } else if (bid < 781) {
        int idx = (bid - 450)*256 + tid;
        if (idx < 3*882*32) {
            int lane = idx & 31, k = (idx >> 5) % 882, fg = idx / (882*32);
            int f = fg*32 + lane;
            g_w1q[idx] = (f < 90) ? w1[f*882 + k] : 0.0f;
        }
    } else {
        for (int i = tid; i < NB*90;  i += 256) g_cflag1[i] = 0;
        for (int i = tid; i < NB*250; i += 256) g_cflag2[i] = 0;
        if (tid < NB) { g_any1[tid] = 0; g_any2[tid] = 0; }
    }
}

// ===========================================================================
// conv1 slow path (essentially never taken): per-t rescan straight from input.
__device__ __noinline__ int conv1_slow(const float* __restrict__ inp,
                                       int b, int f, int y, int x,
                                       const float* __restrict__ w1) {
    const float* wf = w1 + (size_t)f*882;
    for (int t = 1; t < 15; t++) {
        const float* pl = inp + ((size_t)(b*NT + t))*18*1024;
        float cum = 0.0f;
        for (int c = 0; c < 18; c++)
            for (int i = 0; i < 7; i++) {
                int h = y + i - 2;
                if ((unsigned)h >= 32u) continue;
                for (int j = 0; j < 7; j++) {
                    int w = x + j - 2;
                    if ((unsigned)w >= 32u) continue;
                    if (pl[(c << 10) + (h << 5) + w] > 0.5f) cum += wf[c*49 + i*7 + j];
                }
            }
        if (cum > 15.0f) return t;
    }
    return 15;
}

// ===========================================================================
// conv1: lane=filter (32/warp), warp = 4 adjacent x for 2 rows. Masks built
// from the t=0 input plane. Warp-uniform bitmask loop. Fused 2x2 pool+flags.
// grid (4 row-octs, 3 fgroups, NB), 1024 threads.
#define CONV1_SMEM (882*32*4 + 18*14*8 + 8*32*32)
__global__ __launch_bounds__(1024, 1) void k_conv1(const float* __restrict__ inp,
                                                   const float* __restrict__ w1) {
    float*    s_w  = (float*)smem_raw;                          // 112896 B
    uint64_t* s_m  = (uint64_t*)(smem_raw + 882*32*4);          // [18][14]
    int8_t*   s_ft = (int8_t*)(smem_raw + 882*32*4 + 18*14*8);  // [8 r][32 x][32 f]
    int tid = threadIdx.x;
    int rq = blockIdx.x, fg = blockIdx.y, b = blockIdx.z;
    int lane = tid & 31, w = tid >> 5;
    int dy = w >> 3, q = w & 7, x0 = q*4;

    const uint4* wsrc = (const uint4*)(g_w1q + (size_t)fg*882*32);
    uint4* wdst = (uint4*)s_w;
    for (int i = tid; i < 882*32/4; i += 1024) wdst[i] = wsrc[i];

    // row bitmasks from the t=0 plane: bit (w_in+2) set iff input fires at t=0
    if (tid < 252) {
        int c = tid / 14, rr = tid % 14;
        int h = rq*8 + rr - 2;
        uint64_t mask = 0;
        if ((unsigned)h < 32u) {
            const float4* row = (const float4*)(inp + ((size_t)b*NT*18 + c)*1024 + (h << 5));
            uint32_t bits = 0;
#pragma unroll
            for (int k = 0; k < 8; k++) {
                float4 v = row[k];
                bits |= (v.x > 0.5f ? 1u : 0u) << (k*4);
                bits |= (v.y > 0.5f ? 2u : 0u) << (k*4);
                bits |= (v.z > 0.5f ? 4u : 0u) << (k*4);
                bits |= (v.w > 0.5f ? 8u : 0u) << (k*4);
            }
            mask = ((uint64_t)bits) << 2;
        }
        s_m[c*14 + rr] = mask;
    }
    __syncthreads();

    int f = fg*32 + lane;
#pragma unroll
    for (int h2 = 0; h2 < 2; h2++) {
        int r = h2*4 + dy;                  // 0..7
        int y = rq*8 + r;
        float a0 = 0.f, a1 = 0.f, a2 = 0.f, a3 = 0.f;
        if (y < 30) {
            for (int c = 0; c < 18; c++) {
                const uint64_t* mrow = s_m + c*14 + r;
                const float* wc = s_w + c*49*32 + lane;
#pragma unroll
                for (int i = 0; i < 7; i++) {
                    uint32_t wnd = (uint32_t)(mrow[i] >> x0) & 0x3FFu;
                    const float* wi = wc + i*7*32;
                    while (wnd) {
                        int p = __ffs(wnd) - 1;
                        wnd &= wnd - 1;
                        if (p <= 6)           a0 += wi[p*32];
                        if (p >= 1 && p <= 7) a1 += wi[(p-1)*32];
                        if (p >= 2 && p <= 8) a2 += wi[(p-2)*32];
                        if (p >= 3)           a3 += wi[(p-3)*32];
                    }
                }
            }
        }
        float aa[4] = {a0, a1, a2, a3};
#pragma unroll
        for (int k = 0; k < 4; k++) {
            int x = x0 + k;
            int ft = 0;
            if (y < 30 && x < 30 && f < 90)
                ft = (aa[k] > 15.0f) ? 0 : conv1_slow(inp, b, f, y, x, w1);
            s_ft[(r*32 + x)*32 + lane] = (int8_t)ft;
        }
    }
    __syncthreads();

    // fused 2x2 min-pool + channel flags (4 pooled rows per block)
    bool nz = false;
    for (int i2 = tid; i2 < 1920; i2 += 1024) {
        int pf = i2 & 31;
        int rest = i2 >> 5;                 // 0..59
        int pcol = rest % 15;
        int pr   = rest / 15;               // 0..3
        int prow = rq*4 + pr;
        int r0 = pr*2, c0 = pcol*2;
        int v0 = s_ft[(r0*32     + c0  )*32 + pf];
        int v1 = s_ft[(r0*32     + c0+1)*32 + pf];
        int v2 = s_ft[((r0+1)*32 + c0  )*32 + pf];
        int v3 = s_ft[((r0+1)*32 + c0+1)*32 + pf];
        int m0 = v0 < v1 ? v0 : v1;
        int m1 = v2 < v3 ? v2 : v3;
        int pv = m0 < m1 ? m0 : m1;
        int ff = fg*32 + pf;
        if (prow < 15 && ff < 90) {
            g_ft1p[((b*90 + ff)*15 + prow)*16 + pcol] = (int8_t)pv;
            if (pv) { g_cflag1[b*90 + ff] = 1; nz = true; }
        }
    }
    int cnt = __syncthreads_count(nz);
    if (tid == 0 && cnt) atomicAdd(&g_any1[b], 1);
}

// ===========================================================================
// conv2: SAT fast path (skips tile loads when batch all-zero), corrections
// otherwise. Fused 3x3 pool + layer-2 flags. (round-3 proven)
__global__ __launch_bounds__(192) void k_conv2(const float* __restrict__ w2) {
    __shared__ __align__(16) int8_t s_tf[90*240];
    __shared__ float   s_sat[36];
    __shared__ float   s_h[14*192];
    __shared__ uint8_t s_flags[90];
    __shared__ int8_t  s_ftp[169];
    int tid = threadIdx.x;
    int f = blockIdx.x, b = blockIdx.y;
    int any = g_any1[b];

    if (tid < 36) s_sat[tid] = g_wsat2[f*36 + tid];
    if (any) {
        const uint4* src = (const uint4*)(g_ft1p + (size_t)b*90*240);
        uint4* dst = (uint4*)s_tf;
        for (int i = tid; i < 90*240/16; i += 192) dst[i] = src[i];
        if (tid < 90) s_flags[tid] = g_cflag1[b*90 + tid];
        for (int t = 0; t < 14; t++) s_h[t*192 + tid] = 0.0f;
    }
    __syncthreads();

    if (tid < 169) {
        int y = tid / 13, x = tid - y*13;
        int r0 = max(0, y-1), r1 = min(14, y+3);
        int c0 = max(0, x-1), c1 = min(14, x+3);
        int i0 = r0 - (y-1), i1 = r1 - (y-1);
        int j0 = c0 - (x-1), j1 = c1 - (x-1);
        float a0 = s_sat[(i1+1)*6 + (j1+1)] - s_sat[i0*6 + (j1+1)]
                 - s_sat[(i1+1)*6 + j0]     + s_sat[i0*6 + j0];
        int ft;
        if (!any) {
            ft = (a0 > 10.0f) ? 0 : 15;
        } else {
            float* hb = s_h + tid;
            for (int c = 0; c < 90; c++) {
                if (!s_flags[c]) continue;
                const int8_t* tp = s_tf + c*240;
                const float*  wp = w2 + ((size_t)f*90 + c)*25;
                for (int r = r0; r <= r1; r++)
                    for (int cc = c0; cc <= c1; cc++) {
                        int tf = tp[r*16 + cc];
                        if (tf) {
                            float wv = __ldg(wp + (r-(y-1))*5 + (cc-(x-1)));
                            a0 -= wv;
                            if (tf < 15) hb[(tf-1)*192] += wv;
                        }
                    }
            }
            float cum = a0; ft = 15;
            if (cum > 10.0f) ft = 0;
#pragma unroll
            for (int t = 1; t < 15; t++) {
                cum += hb[(t-1)*192];
                if (ft == 15 && cum > 10.0f) ft = t;
            }
        }
        s_ftp[tid] = (int8_t)ft;
    }
    __syncthreads();

    bool nz = false;
    if (tid < 16) {
        int yy = tid >> 2, xx = tid & 3;
        const int8_t* bp = s_ftp + yy*39 + xx*3;
        int v = 15;
#pragma unroll
        for (int dy = 0; dy < 3; dy++)
#pragma unroll
            for (int dx = 0; dx < 3; dx++) {
                int u = bp[dy*13 + dx];
                v = u < v ? u : v;
            }
        g_ft2p[(b*250 + f)*16 + tid] = (int8_t)v;
        nz = (v != 0);
    }
    int cnt = __syncthreads_count(nz);
    if (tid == 0 && cnt) { g_cflag2[b*250 + f] = 1; atomicAdd(&g_any2[b], 1); }
}

// ===========================================================================
// conv3: SAT fast path (skip tile loads if any2==0), else corrections + hist.
__global__ __launch_bounds__(256) void k_conv3(const float* __restrict__ w3,
                                               float* __restrict__ pot) {
    __shared__ __align__(16) int8_t s_tf[250*16];
    __shared__ float   s_sat[16*36];
    __shared__ float   s_h[14*256];
    __shared__ uint8_t s_flags[250];
    int tid = threadIdx.x;
    int fg = blockIdx.x, b = blockIdx.y;
    int any = g_any2[b];

    for (int i = tid; i < 16*36; i += 256) {
        int f = fg*16 + i/36;
        s_sat[i] = (f < 200) ? g_wsat3[f*36 + i%36] : 0.0f;
    }
    if (any) {
        const uint4* src = (const uint4*)(g_ft2p + (size_t)b*250*16);
        for (int i = tid; i < 250; i += 256) ((uint4*)s_tf)[i] = src[i];
        if (tid < 250) s_flags[tid] = g_cflag2[b*250 + tid];
        for (int t = 0; t < 14; t++) s_h[t*256 + tid] = 0.0f;
    }
    __syncthreads();

    int fi = tid >> 4, p = tid & 15;
    int f = fg*16 + fi;
    if (f < 200) {
        int y = p >> 2, x = p & 3;
        int r0 = max(0, y-2), r1 = min(3, y+2);
        int c0 = max(0, x-2), c1 = min(3, x+2);
        int i0 = r0 - (y-2), i1 = r1 - (y-2);
        int j0 = c0 - (x-2), j1 = c1 - (x-2);
        const float* S = s_sat + fi*36;
        float a0 = S[(i1+1)*6 + (j1+1)] - S[i0*6 + (j1+1)]
                 - S[(i1+1)*6 + j0]     + S[i0*6 + j0];
        float* o = pot + ((size_t)b*NT*200 + f)*16 + p;
        if (!any) {
#pragma unroll
            for (int t = 0; t < NT; t++) o[(size_t)t * 3200] = a0;
        } else {
            float* hb = s_h + tid;
            for (int c = 0; c < 250; c++) {
                if (!s_flags[c]) continue;
                const int8_t* tp = s_tf + c*16;
                const float*  wp = w3 + ((size_t)f*250 + c)*25;
                for (int r = r0; r <= r1; r++)
                    for (int cc = c0; cc <= c1; cc++) {
                        int tf = tp[r*4 + cc];
                        if (tf) {
                            float wv = __ldg(wp + (r-(y-2))*5 + (cc-(x-2)));
                            a0 -= wv;
                            if (tf < 15) hb[(tf-1)*256] += wv;
                        }
                    }
            }
            float cum = a0;
#pragma unroll
            for (int t = 0; t < NT; t++) {
                if (t) cum += hb[(t-1)*256];
                o[(size_t)t * 3200] = cum;
            }
        }
    }
}

// ===========================================================================
// winner: argmax over pot3[:,14] > 0 (earliest index on ties), class = feat/20.
__global__ void k_winner(const float* __restrict__ pot, float* __restrict__ cls) {
    __shared__ float s_v[256];
    __shared__ int   s_i[256];
    int b = blockIdx.x, tid = threadIdx.x;
    const float* p = pot + ((size_t)b*NT + 14) * 3200;
    float bv = 0.0f; int bi = 1 << 30;
    for (int i = tid; i < 3200; i += 256) {
        float v = p[i];
        if (v > bv) { bv = v; bi = i; }
    }
    s_v[tid] = bv; s_i[tid] = bi;
    __syncthreads();
    for (int s = 128; s > 0; s >>= 1) {
        if (tid < s) {
            float ov = s_v[tid+s]; int oi = s_i[tid+s];
            if (ov > s_v[tid] || (ov == s_v[tid] && oi < s_i[tid])) {
                s_v[tid] = ov; s_i[tid] = oi;
            }
        }
        __syncthreads();
    }
    if (tid == 0)
        cls[b] = (s_v[0] > 0.0f) ? (float)((s_i[0] >> 4) / 20) : -1.0f;
}

// ===========================================================================
extern "C" void kernel_launch(void* const* d_in, const int* in_sizes, int n_in,
                              void* d_out, int out_size) {
    const float* inp = (const float*)d_in[0];
    const float* w1  = (const float*)d_in[1];
    const float* w2  = (const float*)d_in[2];
    const float* w3  = (const float*)d_in[3];

    float* out = (float*)d_out;
    float* pot = out;
    float* cls = nullptr;
    if (out_size == NB + NB*NT*3200) {   // (cls, pot3) concatenated
        cls = out;
        pot = out + NB;
    }

    static bool attr_set = false;
    if (!attr_set) {
        cudaFuncSetAttribute(k_conv1, cudaFuncAttributeMaxDynamicSharedMemorySize,
                             CONV1_SMEM);
        attr_set = true;
    }

    k_prep <<<782, 256>>>(w1, w2, w3);
    k_conv1<<<dim3(4, 3, NB), 1024, CONV1_SMEM>>>(inp, w1);
    k_conv2<<<dim3(250, NB), 192>>>(w2);
    k_conv3<<<dim3(13, NB), 256>>>(w3, pot);
    if (cls) k_winner<<<NB, 256>>>(pot, cls);
}